// round 3
// baseline (speedup 1.0000x reference)
#include <cuda_runtime.h>
#include <math.h>

#define NE   16
#define NU   8
#define NA   4
#define NSV  256
#define NPV  32
#define NFB  4
#define NDET 16
#define SVO  832   // 3*256 + 2*32
#define S0IN 56    // 3*16 + 2*4

// shared layout (floats)
#define OFF_SV    0                    // 16*256 = 4096
#define OFF_PV    (OFF_SV + 4096)      // 16*16*32 = 8192
#define OFF_MU    (OFF_PV + 8192)      // 256
#define OFF_MD    (OFF_MU + 256)       // 256
#define OFF_PU    (OFF_MD + 256)       // 512
#define OFF_PD    (OFF_PU + 512)       // 512
#define OFF_SIN   (OFF_PD + 512)       // 256
#define OFF_P4    (OFF_SIN + 256)      // 1024
#define OFF_ENV   (OFF_P4 + 1024)      // 16
#define OFF_RS    (OFF_ENV + 16)       // 48
#define OFF_AS    (OFF_RS + 48)        // 12
#define OFF_DET   (OFF_AS + 12)        // 32*65 = 2080
#define OFF_LOGD  (OFF_DET + 2080)     // 32
#define OFF_SIGN  (OFF_LOGD + 32)      // 32
#define SMEM_FLOATS (OFF_SIGN + 32)
#define SMEM_BYTES  (SMEM_FLOATS * 4)

__global__ void __launch_bounds__(256, 2) ansatz_kernel(
    const float* __restrict__ r,    const float* __restrict__ a,
    const float* __restrict__ sW0,  const float* __restrict__ sb0,
    const float* __restrict__ sW,   const float* __restrict__ sb,
    const float* __restrict__ pW0,  const float* __restrict__ pb0,
    const float* __restrict__ pW,   const float* __restrict__ pb,
    const float* __restrict__ vW,   const float* __restrict__ vb,
    const float* __restrict__ wuW,  const float* __restrict__ wub,
    const float* __restrict__ wdW,  const float* __restrict__ wdb,
    const float* __restrict__ wfW,  float* __restrict__ out)
{
    extern __shared__ float sm[];
    float* s_v  = sm + OFF_SV;
    float* p_v  = sm + OFF_PV;
    float* mu   = sm + OFF_MU;
    float* md   = sm + OFF_MD;
    float* pu   = sm + OFF_PU;
    float* pd   = sm + OFF_PD;
    float* s_in = sm + OFF_SIN;
    float* p4   = sm + OFF_P4;
    float* env  = sm + OFF_ENV;
    float* r_s  = sm + OFF_RS;
    float* a_s  = sm + OFF_AS;
    float* detS = sm + OFF_DET;
    float* logd_s = sm + OFF_LOGD;
    float* sign_s = sm + OFF_SIGN;

    const int t = threadIdx.x;
    const int b = blockIdx.x;

    if (t < 48)              r_s[t]      = r[b * 48 + t];
    if (t >= 64 && t < 76)   a_s[t - 64] = a[t - 64];
    __syncthreads();

    // ---------------- embedding ----------------
    {
        int e = t >> 4, f = t & 15, atom = f >> 2, comp = f & 3;
        float dx = r_s[e*3+0] - a_s[atom*3+0];
        float dy = r_s[e*3+1] - a_s[atom*3+1];
        float dz = r_s[e*3+2] - a_s[atom*3+2];
        float v;
        if      (comp == 0) v = dx;
        else if (comp == 1) v = dy;
        else if (comp == 2) v = dz;
        else                v = sqrtf(dx*dx + dy*dy + dz*dz);
        s_in[t] = v;
    }
    if (t < 16) {
        float s = 0.f;
        #pragma unroll
        for (int atom = 0; atom < NA; atom++) {
            float dx = r_s[t*3+0] - a_s[atom*3+0];
            float dy = r_s[t*3+1] - a_s[atom*3+1];
            float dz = r_s[t*3+2] - a_s[atom*3+2];
            s += expf(-sqrtf(dx*dx + dy*dy + dz*dz));
        }
        env[t] = s;
    }
    for (int idx = t; idx < 1024; idx += 256) {
        int pr = idx >> 2, comp = idx & 3;
        int i = pr >> 4, j = pr & 15;
        float dx = r_s[j*3+0] - r_s[i*3+0];
        float dy = r_s[j*3+1] - r_s[i*3+1];
        float dz = r_s[j*3+2] - r_s[i*3+2];
        float v;
        if      (comp == 0) v = dx;
        else if (comp == 1) v = dy;
        else if (comp == 2) v = dz;
        else {
            float o = (i == j) ? 1.f : 0.f;
            float ex = dx + o, ey = dy + o, ez = dz + o;
            v = sqrtf(ex*ex + ey*ey + ez*ez);
        }
        p4[idx] = v;
    }
    __syncthreads();

    // ---------------- stats for layer 0 (16-wide s, 4-wide p) ----------------
    if (t < 16) {
        float s = 0.f;
        #pragma unroll
        for (int e = 0; e < NU; e++) s += s_in[e*16 + t];
        mu[t] = s * 0.125f;
    } else if (t < 32) {
        int f = t - 16; float s = 0.f;
        #pragma unroll
        for (int e = NU; e < NE; e++) s += s_in[e*16 + f];
        md[f] = s * 0.125f;
    } else if (t < 96) {
        int idx = t - 32; int j = idx >> 2, c = idx & 3; float s = 0.f;
        #pragma unroll
        for (int i = 0; i < NU; i++) s += p4[(i*16 + j)*4 + c];
        pu[j*4 + c] = s * 0.125f;
    } else if (t < 160) {
        int idx = t - 96; int j = idx >> 2, c = idx & 3; float s = 0.f;
        #pragma unroll
        for (int i = NU; i < NE; i++) s += p4[(i*16 + j)*4 + c];
        pd[j*4 + c] = s * 0.125f;
    }
    __syncthreads();

    // ---------------- layer 0, s-stream ----------------
    {
        const int c = t;
        float common = sb0[c];
        #pragma unroll
        for (int k = 0; k < 16; k++)
            common += mu[k] * sW0[(16 + k)*NSV + c] + md[k] * sW0[(32 + k)*NSV + c];
        float acc[NE];
        #pragma unroll
        for (int e = 0; e < NE; e++) acc[e] = 0.f;
        #pragma unroll
        for (int k = 0; k < 16; k++) {
            float w = sW0[k*NSV + c];
            #pragma unroll
            for (int e = 0; e < NE; e++) acc[e] += s_in[e*16 + k] * w;
        }
        #pragma unroll
        for (int k = 0; k < 4; k++) {
            float wA = sW0[(48 + k)*NSV + c];
            float wB = sW0[(52 + k)*NSV + c];
            #pragma unroll
            for (int e = 0; e < NE; e++)
                acc[e] += pu[e*4 + k] * wA + pd[e*4 + k] * wB;
        }
        #pragma unroll
        for (int e = 0; e < NE; e++)
            s_v[e*NSV + c] = tanhf(acc[e] + common);
    }
    // ---------------- layer 0, p-stream ----------------
    {
        const int c = t & 31, wp = t >> 5;
        for (int pr = wp; pr < 256; pr += 8) {
            float acc = pb0[c];
            #pragma unroll
            for (int k = 0; k < 4; k++) acc += p4[pr*4 + k] * pW0[k*NPV + c];
            p_v[pr*NPV + c] = tanhf(acc);
        }
    }
    __syncthreads();

    // ---------------- full stats helper (inline twice via loop) ----------------
    // stats after layer 0
    {
        const int c = t;
        float su = 0.f, sd2 = 0.f;
        #pragma unroll
        for (int e = 0; e < NU; e++)  su  += s_v[e*NSV + c];
        #pragma unroll
        for (int e = NU; e < NE; e++) sd2 += s_v[e*NSV + c];
        mu[c] = su * 0.125f; md[c] = sd2 * 0.125f;
        for (int idx = t; idx < 512; idx += 256) {
            int j = idx >> 5, c2 = idx & 31;
            float pa = 0.f, pb2 = 0.f;
            #pragma unroll
            for (int i = 0; i < NU; i++)  pa  += p_v[(i*16 + j)*NPV + c2];
            #pragma unroll
            for (int i = NU; i < NE; i++) pb2 += p_v[(i*16 + j)*NPV + c2];
            pu[idx] = pa * 0.125f; pd[idx] = pb2 * 0.125f;
        }
    }
    __syncthreads();

    // ---------------- residual layers + final v layer ----------------
    for (int L = 0; L <= NFB; L++) {
        const bool isV = (L == NFB);
        const float* W    = isV ? vW : (sW + (size_t)L * SVO * NSV);
        const float* bias = isV ? vb : (sb + L * NSV);
        const int c = t;

        float common = bias[c];
        {
            const float* Wmu = W + 256*NSV + c;
            const float* Wmd = W + 512*NSV + c;
            float c0 = 0.f, c1 = 0.f;
            for (int k = 0; k < 256; k += 4) {
                float4 m4 = *(const float4*)(mu + k);
                float4 d4 = *(const float4*)(md + k);
                c0 += m4.x*Wmu[(k+0)*NSV] + m4.y*Wmu[(k+1)*NSV]
                    + m4.z*Wmu[(k+2)*NSV] + m4.w*Wmu[(k+3)*NSV];
                c1 += d4.x*Wmd[(k+0)*NSV] + d4.y*Wmd[(k+1)*NSV]
                    + d4.z*Wmd[(k+2)*NSV] + d4.w*Wmd[(k+3)*NSV];
            }
            common += c0 + c1;
        }
        float acc[NE];
        #pragma unroll
        for (int e = 0; e < NE; e++) acc[e] = 0.f;
        for (int k = 0; k < 256; k += 4) {
            float w0 = W[(k+0)*NSV + c];
            float w1 = W[(k+1)*NSV + c];
            float w2 = W[(k+2)*NSV + c];
            float w3 = W[(k+3)*NSV + c];
            #pragma unroll
            for (int e = 0; e < NE; e++) {
                float4 s4 = *(const float4*)(s_v + e*NSV + k);
                acc[e] += s4.x*w0 + s4.y*w1 + s4.z*w2 + s4.w*w3;
            }
        }
        {
            const float* Wpu = W + 768*NSV;
            const float* Wpd = W + 800*NSV;
            for (int k = 0; k < 32; k += 4) {
                float u0 = Wpu[(k+0)*NSV + c], u1 = Wpu[(k+1)*NSV + c];
                float u2 = Wpu[(k+2)*NSV + c], u3 = Wpu[(k+3)*NSV + c];
                float v0 = Wpd[(k+0)*NSV + c], v1 = Wpd[(k+1)*NSV + c];
                float v2 = Wpd[(k+2)*NSV + c], v3 = Wpd[(k+3)*NSV + c];
                #pragma unroll
                for (int e = 0; e < NE; e++) {
                    float4 a4 = *(const float4*)(pu + e*NPV + k);
                    float4 b4 = *(const float4*)(pd + e*NPV + k);
                    acc[e] += a4.x*u0 + a4.y*u1 + a4.z*u2 + a4.w*u3
                            + b4.x*v0 + b4.y*v1 + b4.z*v2 + b4.w*v3;
                }
            }
        }

        if (!isV) {
            // p-stream residual layer: warp-private pairs, in-place update
            const int c2 = t & 31, wp = t >> 5;
            const float* PW = pW + L * NPV * NPV;
            const float pbias = pb[L*NPV + c2];
            for (int pr = wp; pr < 256; pr += 8) {
                float pacc = pbias;
                for (int k = 0; k < 32; k += 4) {
                    float4 v4 = *(const float4*)(p_v + pr*NPV + k);
                    pacc += v4.x*PW[(k+0)*NPV + c2] + v4.y*PW[(k+1)*NPV + c2]
                          + v4.z*PW[(k+2)*NPV + c2] + v4.w*PW[(k+3)*NPV + c2];
                }
                p_v[pr*NPV + c2] = tanhf(pacc) + p_v[pr*NPV + c2];
            }
        }

        __syncthreads();   // all reads of s_v complete
        if (!isV) {
            #pragma unroll
            for (int e = 0; e < NE; e++)
                s_v[e*NSV + c] = tanhf(acc[e] + common) + s_v[e*NSV + c];
        } else {
            #pragma unroll
            for (int e = 0; e < NE; e++)
                s_v[e*NSV + c] = tanhf(acc[e] + common);
        }
        __syncthreads();

        if (!isV) {
            // recompute stats for next layer
            float su = 0.f, sd2 = 0.f;
            #pragma unroll
            for (int e = 0; e < NU; e++)  su  += s_v[e*NSV + c];
            #pragma unroll
            for (int e = NU; e < NE; e++) sd2 += s_v[e*NSV + c];
            mu[c] = su * 0.125f; md[c] = sd2 * 0.125f;
            for (int idx = t; idx < 512; idx += 256) {
                int j = idx >> 5, cc = idx & 31;
                float pa = 0.f, pb2 = 0.f;
                #pragma unroll
                for (int i = 0; i < NU; i++)  pa  += p_v[(i*16 + j)*NPV + cc];
                #pragma unroll
                for (int i = NU; i < NE; i++) pb2 += p_v[(i*16 + j)*NPV + cc];
                pu[idx] = pa * 0.125f; pd[idx] = pb2 * 0.125f;
            }
            __syncthreads();
        }
    }

    // ---------------- orbitals ----------------
    {
        const bool up = (t < 128);
        const int col = up ? t : t - 128;
        const float* W    = up ? wuW : wdW;
        const float* bias = up ? wub : wdb;
        const int ebase = up ? 0 : NU;
        const int d = col & 15, j = col >> 4;
        const int detIdx = (up ? 0 : NDET) + d;
        for (int ii = 0; ii < 8; ii++) {
            const int i = ebase + ii;
            float acc = bias[col];
            for (int k = 0; k < 256; k += 4) {
                float4 s4 = *(const float4*)(s_v + i*NSV + k);
                acc += s4.x*W[(k+0)*128 + col] + s4.y*W[(k+1)*128 + col]
                     + s4.z*W[(k+2)*128 + col] + s4.w*W[(k+3)*128 + col];
            }
            detS[detIdx*65 + ii*8 + j] = acc * env[i];
        }
    }
    __syncthreads();

    // ---------------- slogdet: 8x8 LU with partial pivoting ----------------
    if (t < 32) {
        float* M = detS + t * 65;
        float sg = 1.f, ld = 0.f;
        for (int k = 0; k < 8; k++) {
            int p = k; float best = fabsf(M[k*8 + k]);
            for (int rr2 = k + 1; rr2 < 8; rr2++) {
                float v = fabsf(M[rr2*8 + k]);
                if (v > best) { best = v; p = rr2; }
            }
            if (p != k) {
                for (int cc = 0; cc < 8; cc++) {
                    float tmp = M[k*8 + cc]; M[k*8 + cc] = M[p*8 + cc]; M[p*8 + cc] = tmp;
                }
                sg = -sg;
            }
            float piv = M[k*8 + k];
            if (piv < 0.f) sg = -sg;
            ld += logf(fabsf(piv));
            float inv = 1.f / piv;
            for (int rr2 = k + 1; rr2 < 8; rr2++) {
                float f = M[rr2*8 + k] * inv;
                for (int cc = k + 1; cc < 8; cc++) M[rr2*8 + cc] -= f * M[k*8 + cc];
            }
        }
        logd_s[t] = ld; sign_s[t] = sg;
    }
    __syncthreads();

    // ---------------- combine ----------------
    if (t == 0) {
        float lds[NDET], sgs[NDET], m = -1e30f;
        #pragma unroll
        for (int d = 0; d < NDET; d++) {
            lds[d] = logd_s[d] + logd_s[NDET + d];
            sgs[d] = sign_s[d] * sign_s[NDET + d];
            if (lds[d] > m) m = lds[d];
        }
        float sum = 0.f;
        #pragma unroll
        for (int d = 0; d < NDET; d++)
            sum += sgs[d] * expf(lds[d] - m) * wfW[d];
        out[b] = logf(fabsf(sum)) + m;
    }
}

extern "C" void kernel_launch(void* const* d_in, const int* in_sizes, int n_in,
                              void* d_out, int out_size)
{
    const float* r   = (const float*)d_in[0];
    const float* a   = (const float*)d_in[1];
    const float* sW0 = (const float*)d_in[2];
    const float* sb0 = (const float*)d_in[3];
    const float* sW  = (const float*)d_in[4];
    const float* sb  = (const float*)d_in[5];
    const float* pW0 = (const float*)d_in[6];
    const float* pb0 = (const float*)d_in[7];
    const float* pW  = (const float*)d_in[8];
    const float* pb  = (const float*)d_in[9];
    const float* vW  = (const float*)d_in[10];
    const float* vb  = (const float*)d_in[11];
    const float* wuW = (const float*)d_in[12];
    const float* wub = (const float*)d_in[13];
    const float* wdW = (const float*)d_in[14];
    const float* wdb = (const float*)d_in[15];
    const float* wfW = (const float*)d_in[16];
    float* out = (float*)d_out;

    const int B = in_sizes[0] / (NE * 3);

    cudaFuncSetAttribute(ansatz_kernel,
                         cudaFuncAttributeMaxDynamicSharedMemorySize, SMEM_BYTES);
    ansatz_kernel<<<B, 256, SMEM_BYTES>>>(r, a, sW0, sb0, sW, sb, pW0, pb0,
                                          pW, pb, vW, vb, wuW, wub, wdW, wdb,
                                          wfW, out);
}

// round 4
// speedup vs baseline: 1.1827x; 1.1827x over previous
#include <cuda_runtime.h>
#include <math.h>

#define NE   16
#define NU   8
#define NA   4
#define NSV  256
#define NPV  32
#define NFB  4
#define NDET 16
#define SVO  832   // 3*256 + 2*32

// shared layout (floats)
#define OFF_SV    0                    // 16*256 = 4096
#define OFF_PV    (OFF_SV + 4096)      // 16*16*32 = 8192  (det scratch aliases here)
#define OFF_MU    (OFF_PV + 8192)      // 256
#define OFF_MD    (OFF_MU + 256)       // 256
#define OFF_PU    (OFF_MD + 256)       // 512
#define OFF_PD    (OFF_PU + 512)       // 512
#define OFF_SIN   (OFF_PD + 512)       // 256
#define OFF_P4    (OFF_SIN + 256)      // 1024
#define OFF_ENV   (OFF_P4 + 1024)      // 16
#define OFF_RS    (OFF_ENV + 16)       // 48
#define OFF_AS    (OFF_RS + 48)        // 12
#define OFF_LOGD  (OFF_AS + 12)        // 32
#define OFF_SIGN  (OFF_LOGD + 32)      // 32
#define SMEM_FLOATS (OFF_SIGN + 32)
#define SMEM_BYTES  (SMEM_FLOATS * 4)

__device__ __forceinline__ float tanh_fast(float x) {
    // |err| ~ 2e-6 rel; clamp keeps __expf / __fdividef in safe range
    x = fminf(15.f, fmaxf(-15.f, x));
    float e = __expf(2.0f * x);
    return 1.0f - __fdividef(2.0f, e + 1.0f);
}

__global__ void __launch_bounds__(256, 3) ansatz_kernel(
    const float* __restrict__ r,    const float* __restrict__ a,
    const float* __restrict__ sW0,  const float* __restrict__ sb0,
    const float* __restrict__ sW,   const float* __restrict__ sb,
    const float* __restrict__ pW0,  const float* __restrict__ pb0,
    const float* __restrict__ pW,   const float* __restrict__ pb,
    const float* __restrict__ vW,   const float* __restrict__ vb,
    const float* __restrict__ wuW,  const float* __restrict__ wub,
    const float* __restrict__ wdW,  const float* __restrict__ wdb,
    const float* __restrict__ wfW,  float* __restrict__ out)
{
    extern __shared__ float sm[];
    float* s_v  = sm + OFF_SV;
    float* p_v  = sm + OFF_PV;
    float* mu   = sm + OFF_MU;
    float* md   = sm + OFF_MD;
    float* pu   = sm + OFF_PU;
    float* pd   = sm + OFF_PD;
    float* s_in = sm + OFF_SIN;
    float* p4   = sm + OFF_P4;
    float* env  = sm + OFF_ENV;
    float* r_s  = sm + OFF_RS;
    float* a_s  = sm + OFF_AS;
    float* detS = sm + OFF_PV;     // alias: p_v dead by orbital phase (32*65=2080 <= 8192)
    float* logd_s = sm + OFF_LOGD;
    float* sign_s = sm + OFF_SIGN;

    const int t = threadIdx.x;
    const int b = blockIdx.x;

    if (t < 48)              r_s[t]      = r[b * 48 + t];
    if (t >= 64 && t < 76)   a_s[t - 64] = a[t - 64];
    __syncthreads();

    // ---------------- embedding ----------------
    {
        int e = t >> 4, f = t & 15, atom = f >> 2, comp = f & 3;
        float dx = r_s[e*3+0] - a_s[atom*3+0];
        float dy = r_s[e*3+1] - a_s[atom*3+1];
        float dz = r_s[e*3+2] - a_s[atom*3+2];
        float v;
        if      (comp == 0) v = dx;
        else if (comp == 1) v = dy;
        else if (comp == 2) v = dz;
        else                v = sqrtf(dx*dx + dy*dy + dz*dz);
        s_in[t] = v;
    }
    if (t < 16) {
        float s = 0.f;
        #pragma unroll
        for (int atom = 0; atom < NA; atom++) {
            float dx = r_s[t*3+0] - a_s[atom*3+0];
            float dy = r_s[t*3+1] - a_s[atom*3+1];
            float dz = r_s[t*3+2] - a_s[atom*3+2];
            s += __expf(-sqrtf(dx*dx + dy*dy + dz*dz));
        }
        env[t] = s;
    }
    for (int idx = t; idx < 1024; idx += 256) {
        int pr = idx >> 2, comp = idx & 3;
        int i = pr >> 4, j = pr & 15;
        float dx = r_s[j*3+0] - r_s[i*3+0];
        float dy = r_s[j*3+1] - r_s[i*3+1];
        float dz = r_s[j*3+2] - r_s[i*3+2];
        float v;
        if      (comp == 0) v = dx;
        else if (comp == 1) v = dy;
        else if (comp == 2) v = dz;
        else {
            float o = (i == j) ? 1.f : 0.f;
            float ex = dx + o, ey = dy + o, ez = dz + o;
            v = sqrtf(ex*ex + ey*ey + ez*ez);
        }
        p4[idx] = v;
    }
    __syncthreads();

    // ---------------- stats for layer 0 ----------------
    if (t < 16) {
        float s = 0.f;
        #pragma unroll
        for (int e = 0; e < NU; e++) s += s_in[e*16 + t];
        mu[t] = s * 0.125f;
    } else if (t < 32) {
        int f = t - 16; float s = 0.f;
        #pragma unroll
        for (int e = NU; e < NE; e++) s += s_in[e*16 + f];
        md[f] = s * 0.125f;
    } else if (t < 96) {
        int idx = t - 32; int j = idx >> 2, c = idx & 3; float s = 0.f;
        #pragma unroll
        for (int i = 0; i < NU; i++) s += p4[(i*16 + j)*4 + c];
        pu[j*4 + c] = s * 0.125f;
    } else if (t < 160) {
        int idx = t - 96; int j = idx >> 2, c = idx & 3; float s = 0.f;
        #pragma unroll
        for (int i = NU; i < NE; i++) s += p4[(i*16 + j)*4 + c];
        pd[j*4 + c] = s * 0.125f;
    }
    __syncthreads();

    // ---------------- layer 0, s-stream ----------------
    {
        const int c = t;
        float common = sb0[c];
        #pragma unroll
        for (int k = 0; k < 16; k++)
            common += mu[k] * sW0[(16 + k)*NSV + c] + md[k] * sW0[(32 + k)*NSV + c];
        float acc[NE];
        #pragma unroll
        for (int e = 0; e < NE; e++) acc[e] = 0.f;
        #pragma unroll
        for (int k = 0; k < 16; k++) {
            float w = sW0[k*NSV + c];
            #pragma unroll
            for (int e = 0; e < NE; e++) acc[e] += s_in[e*16 + k] * w;
        }
        #pragma unroll
        for (int k = 0; k < 4; k++) {
            float wA = sW0[(48 + k)*NSV + c];
            float wB = sW0[(52 + k)*NSV + c];
            #pragma unroll
            for (int e = 0; e < NE; e++)
                acc[e] += pu[e*4 + k] * wA + pd[e*4 + k] * wB;
        }
        #pragma unroll
        for (int e = 0; e < NE; e++)
            s_v[e*NSV + c] = tanh_fast(acc[e] + common);
    }
    // ---------------- layer 0, p-stream (weights hoisted) ----------------
    {
        const int c = t & 31, wp = t >> 5;
        float w0 = pW0[0*NPV + c], w1 = pW0[1*NPV + c];
        float w2 = pW0[2*NPV + c], w3 = pW0[3*NPV + c];
        const float pbias = pb0[c];
        for (int pr = wp; pr < 256; pr += 8) {
            float4 q = *(const float4*)(p4 + pr*4);
            p_v[pr*NPV + c] = tanh_fast(pbias + q.x*w0 + q.y*w1 + q.z*w2 + q.w*w3);
        }
    }
    __syncthreads();

    // ---------------- stats after layer 0 ----------------
    {
        const int c = t;
        float su = 0.f, sd2 = 0.f;
        #pragma unroll
        for (int e = 0; e < NU; e++)  su  += s_v[e*NSV + c];
        #pragma unroll
        for (int e = NU; e < NE; e++) sd2 += s_v[e*NSV + c];
        mu[c] = su * 0.125f; md[c] = sd2 * 0.125f;
        for (int idx = t; idx < 512; idx += 256) {
            int j = idx >> 5, c2 = idx & 31;
            float pa = 0.f, pb2 = 0.f;
            #pragma unroll
            for (int i = 0; i < NU; i++)  pa  += p_v[(i*16 + j)*NPV + c2];
            #pragma unroll
            for (int i = NU; i < NE; i++) pb2 += p_v[(i*16 + j)*NPV + c2];
            pu[idx] = pa * 0.125f; pd[idx] = pb2 * 0.125f;
        }
    }
    __syncthreads();

    // ---------------- residual layers + final v layer ----------------
    for (int L = 0; L <= NFB; L++) {
        const bool isV = (L == NFB);
        const float* W    = isV ? vW : (sW + (size_t)L * SVO * NSV);
        const float* bias = isV ? vb : (sb + L * NSV);
        const int c = t;

        float common = bias[c];
        {
            const float* Wmu = W + 256*NSV + c;
            const float* Wmd = W + 512*NSV + c;
            float c0 = 0.f, c1 = 0.f;
            for (int k = 0; k < 256; k += 4) {
                float4 m4 = *(const float4*)(mu + k);
                float4 d4 = *(const float4*)(md + k);
                c0 += m4.x*Wmu[(k+0)*NSV] + m4.y*Wmu[(k+1)*NSV]
                    + m4.z*Wmu[(k+2)*NSV] + m4.w*Wmu[(k+3)*NSV];
                c1 += d4.x*Wmd[(k+0)*NSV] + d4.y*Wmd[(k+1)*NSV]
                    + d4.z*Wmd[(k+2)*NSV] + d4.w*Wmd[(k+3)*NSV];
            }
            common += c0 + c1;
        }
        float acc[NE];
        #pragma unroll
        for (int e = 0; e < NE; e++) acc[e] = 0.f;
        for (int k = 0; k < 256; k += 4) {
            float w0 = W[(k+0)*NSV + c];
            float w1 = W[(k+1)*NSV + c];
            float w2 = W[(k+2)*NSV + c];
            float w3 = W[(k+3)*NSV + c];
            #pragma unroll
            for (int e = 0; e < NE; e++) {
                float4 s4 = *(const float4*)(s_v + e*NSV + k);
                acc[e] += s4.x*w0 + s4.y*w1 + s4.z*w2 + s4.w*w3;
            }
        }
        {
            const float* Wpu = W + 768*NSV;
            const float* Wpd = W + 800*NSV;
            for (int k = 0; k < 32; k += 4) {
                float u0 = Wpu[(k+0)*NSV + c], u1 = Wpu[(k+1)*NSV + c];
                float u2 = Wpu[(k+2)*NSV + c], u3 = Wpu[(k+3)*NSV + c];
                float v0 = Wpd[(k+0)*NSV + c], v1 = Wpd[(k+1)*NSV + c];
                float v2 = Wpd[(k+2)*NSV + c], v3 = Wpd[(k+3)*NSV + c];
                #pragma unroll
                for (int e = 0; e < NE; e++) {
                    float4 a4 = *(const float4*)(pu + e*NPV + k);
                    float4 b4 = *(const float4*)(pd + e*NPV + k);
                    acc[e] += a4.x*u0 + a4.y*u1 + a4.z*u2 + a4.w*u3
                            + b4.x*v0 + b4.y*v1 + b4.z*v2 + b4.w*v3;
                }
            }
        }

        if (!isV) {
            // p-stream residual layer: weights hoisted into registers once
            const int c2 = t & 31, wp = t >> 5;
            const float* PW = pW + L * NPV * NPV + c2;
            float pw[32];
            #pragma unroll
            for (int k = 0; k < 32; k++) pw[k] = PW[k*NPV];
            const float pbias = pb[L*NPV + c2];
            for (int pr = wp; pr < 256; pr += 8) {
                float pacc = pbias;
                #pragma unroll
                for (int k = 0; k < 32; k += 4) {
                    float4 v4 = *(const float4*)(p_v + pr*NPV + k);
                    pacc += v4.x*pw[k] + v4.y*pw[k+1] + v4.z*pw[k+2] + v4.w*pw[k+3];
                }
                p_v[pr*NPV + c2] = tanh_fast(pacc) + p_v[pr*NPV + c2];
            }
        }

        __syncthreads();   // all reads of s_v complete
        if (!isV) {
            #pragma unroll
            for (int e = 0; e < NE; e++)
                s_v[e*NSV + c] = tanh_fast(acc[e] + common) + s_v[e*NSV + c];
        } else {
            #pragma unroll
            for (int e = 0; e < NE; e++)
                s_v[e*NSV + c] = tanh_fast(acc[e] + common);
        }
        __syncthreads();

        if (!isV) {
            float su = 0.f, sd2 = 0.f;
            #pragma unroll
            for (int e = 0; e < NU; e++)  su  += s_v[e*NSV + c];
            #pragma unroll
            for (int e = NU; e < NE; e++) sd2 += s_v[e*NSV + c];
            mu[c] = su * 0.125f; md[c] = sd2 * 0.125f;
            for (int idx = t; idx < 512; idx += 256) {
                int j = idx >> 5, cc = idx & 31;
                float pa = 0.f, pb2 = 0.f;
                #pragma unroll
                for (int i = 0; i < NU; i++)  pa  += p_v[(i*16 + j)*NPV + cc];
                #pragma unroll
                for (int i = NU; i < NE; i++) pb2 += p_v[(i*16 + j)*NPV + cc];
                pu[idx] = pa * 0.125f; pd[idx] = pb2 * 0.125f;
            }
            __syncthreads();
        }
    }
    // NOTE: p_v is dead from here on; detS aliases its storage.

    // ---------------- orbitals (k-outer, weights loaded once) ----------------
    {
        const bool up = (t < 128);
        const int col = up ? t : t - 128;
        const float* W    = up ? wuW : wdW;
        const float* bias = up ? wub : wdb;
        const int ebase = up ? 0 : NU;
        const int d = col & 15, j = col >> 4;
        const int detIdx = (up ? 0 : NDET) + d;

        float acc[8];
        #pragma unroll
        for (int ii = 0; ii < 8; ii++) acc[ii] = 0.f;
        for (int k = 0; k < 256; k += 4) {
            float w0 = W[(k+0)*128 + col];
            float w1 = W[(k+1)*128 + col];
            float w2 = W[(k+2)*128 + col];
            float w3 = W[(k+3)*128 + col];
            #pragma unroll
            for (int ii = 0; ii < 8; ii++) {
                float4 s4 = *(const float4*)(s_v + (ebase+ii)*NSV + k);
                acc[ii] += s4.x*w0 + s4.y*w1 + s4.z*w2 + s4.w*w3;
            }
        }
        float bs = bias[col];
        #pragma unroll
        for (int ii = 0; ii < 8; ii++)
            detS[detIdx*65 + ii*8 + j] = (acc[ii] + bs) * env[ebase + ii];
    }
    __syncthreads();

    // ---------------- slogdet: 8x8 LU with partial pivoting ----------------
    if (t < 32) {
        float* M = detS + t * 65;
        float sg = 1.f, ld = 0.f;
        for (int k = 0; k < 8; k++) {
            int p = k; float best = fabsf(M[k*8 + k]);
            for (int rr2 = k + 1; rr2 < 8; rr2++) {
                float v = fabsf(M[rr2*8 + k]);
                if (v > best) { best = v; p = rr2; }
            }
            if (p != k) {
                for (int cc = 0; cc < 8; cc++) {
                    float tmp = M[k*8 + cc]; M[k*8 + cc] = M[p*8 + cc]; M[p*8 + cc] = tmp;
                }
                sg = -sg;
            }
            float piv = M[k*8 + k];
            if (piv < 0.f) sg = -sg;
            ld += logf(fabsf(piv));
            float inv = 1.f / piv;
            for (int rr2 = k + 1; rr2 < 8; rr2++) {
                float f = M[rr2*8 + k] * inv;
                for (int cc = k + 1; cc < 8; cc++) M[rr2*8 + cc] -= f * M[k*8 + cc];
            }
        }
        logd_s[t] = ld; sign_s[t] = sg;
    }
    __syncthreads();

    // ---------------- combine ----------------
    if (t == 0) {
        float lds[NDET], sgs[NDET], m = -1e30f;
        #pragma unroll
        for (int d = 0; d < NDET; d++) {
            lds[d] = logd_s[d] + logd_s[NDET + d];
            sgs[d] = sign_s[d] * sign_s[NDET + d];
            if (lds[d] > m) m = lds[d];
        }
        float sum = 0.f;
        #pragma unroll
        for (int d = 0; d < NDET; d++)
            sum += sgs[d] * expf(lds[d] - m) * wfW[d];
        out[b] = logf(fabsf(sum)) + m;
    }
}

extern "C" void kernel_launch(void* const* d_in, const int* in_sizes, int n_in,
                              void* d_out, int out_size)
{
    const float* r   = (const float*)d_in[0];
    const float* a   = (const float*)d_in[1];
    const float* sW0 = (const float*)d_in[2];
    const float* sb0 = (const float*)d_in[3];
    const float* sW  = (const float*)d_in[4];
    const float* sb  = (const float*)d_in[5];
    const float* pW0 = (const float*)d_in[6];
    const float* pb0 = (const float*)d_in[7];
    const float* pW  = (const float*)d_in[8];
    const float* pb  = (const float*)d_in[9];
    const float* vW  = (const float*)d_in[10];
    const float* vb  = (const float*)d_in[11];
    const float* wuW = (const float*)d_in[12];
    const float* wub = (const float*)d_in[13];
    const float* wdW = (const float*)d_in[14];
    const float* wdb = (const float*)d_in[15];
    const float* wfW = (const float*)d_in[16];
    float* out = (float*)d_out;

    const int B = in_sizes[0] / (NE * 3);

    cudaFuncSetAttribute(ansatz_kernel,
                         cudaFuncAttributeMaxDynamicSharedMemorySize, SMEM_BYTES);
    ansatz_kernel<<<B, 256, SMEM_BYTES>>>(r, a, sW0, sb0, sW, sb, pW0, pb0,
                                          pW, pb, vW, vb, wuW, wub, wdW, wdb,
                                          wfW, out);
}

// round 5
// speedup vs baseline: 1.3756x; 1.1631x over previous
#include <cuda_runtime.h>
#include <math.h>

#define NE   16
#define NU   8
#define NA   4
#define NSV  256
#define NPV  32
#define NFB  4
#define NDET 16
#define SVO  832   // 3*256 + 2*32

// shared layout (floats)
#define OFF_SV    0                    // 16*256 = 4096
#define OFF_PV    (OFF_SV + 4096)      // 16*16*32 = 8192  (det scratch aliases here)
#define OFF_MU    (OFF_PV + 8192)      // 256
#define OFF_MD    (OFF_MU + 256)       // 256
#define OFF_PU    (OFF_MD + 256)       // 512
#define OFF_PD    (OFF_PU + 512)       // 512
#define OFF_SIN   (OFF_PD + 512)       // 256
#define OFF_P4    (OFF_SIN + 256)      // 1024  (com[2][256] aliases here after layer 0)
#define OFF_ENV   (OFF_P4 + 1024)      // 16
#define OFF_RS    (OFF_ENV + 16)       // 48
#define OFF_AS    (OFF_RS + 48)        // 12
#define OFF_LOGD  (OFF_AS + 12)        // 32
#define OFF_SIGN  (OFF_LOGD + 32)      // 32
#define SMEM_FLOATS (OFF_SIGN + 32)
#define SMEM_BYTES  (SMEM_FLOATS * 4)

__device__ __forceinline__ float tanh_fast(float x) {
    x = fminf(15.f, fmaxf(-15.f, x));
    float e = __expf(2.0f * x);
    return 1.0f - __fdividef(2.0f, e + 1.0f);
}

__global__ void __launch_bounds__(256, 3) ansatz_kernel(
    const float* __restrict__ r,    const float* __restrict__ a,
    const float* __restrict__ sW0,  const float* __restrict__ sb0,
    const float* __restrict__ sW,   const float* __restrict__ sb,
    const float* __restrict__ pW0,  const float* __restrict__ pb0,
    const float* __restrict__ pW,   const float* __restrict__ pb,
    const float* __restrict__ vW,   const float* __restrict__ vb,
    const float* __restrict__ wuW,  const float* __restrict__ wub,
    const float* __restrict__ wdW,  const float* __restrict__ wdb,
    const float* __restrict__ wfW,  float* __restrict__ out)
{
    extern __shared__ float sm[];
    float* s_v  = sm + OFF_SV;
    float* p_v  = sm + OFF_PV;
    float* mu   = sm + OFF_MU;
    float* md   = sm + OFF_MD;
    float* pu   = sm + OFF_PU;
    float* pd   = sm + OFF_PD;
    float* s_in = sm + OFF_SIN;
    float* p4   = sm + OFF_P4;
    float* com  = sm + OFF_P4;     // alias: p4 dead after layer-0 (2*256 <= 1024)
    float* env  = sm + OFF_ENV;
    float* r_s  = sm + OFF_RS;
    float* a_s  = sm + OFF_AS;
    float* detS = sm + OFF_PV;     // alias: p_v dead by orbital phase (32*65=2080 <= 8192)
    float* logd_s = sm + OFF_LOGD;
    float* sign_s = sm + OFF_SIGN;

    const int t = threadIdx.x;
    const int b = blockIdx.x;

    if (t < 48)              r_s[t]      = r[b * 48 + t];
    if (t >= 64 && t < 76)   a_s[t - 64] = a[t - 64];
    __syncthreads();

    // ---------------- embedding ----------------
    {
        int e = t >> 4, f = t & 15, atom = f >> 2, comp = f & 3;
        float dx = r_s[e*3+0] - a_s[atom*3+0];
        float dy = r_s[e*3+1] - a_s[atom*3+1];
        float dz = r_s[e*3+2] - a_s[atom*3+2];
        float v;
        if      (comp == 0) v = dx;
        else if (comp == 1) v = dy;
        else if (comp == 2) v = dz;
        else                v = sqrtf(dx*dx + dy*dy + dz*dz);
        s_in[t] = v;
    }
    if (t < 16) {
        float s = 0.f;
        #pragma unroll
        for (int atom = 0; atom < NA; atom++) {
            float dx = r_s[t*3+0] - a_s[atom*3+0];
            float dy = r_s[t*3+1] - a_s[atom*3+1];
            float dz = r_s[t*3+2] - a_s[atom*3+2];
            s += __expf(-sqrtf(dx*dx + dy*dy + dz*dz));
        }
        env[t] = s;
    }
    for (int idx = t; idx < 1024; idx += 256) {
        int pr = idx >> 2, comp = idx & 3;
        int i = pr >> 4, j = pr & 15;
        float dx = r_s[j*3+0] - r_s[i*3+0];
        float dy = r_s[j*3+1] - r_s[i*3+1];
        float dz = r_s[j*3+2] - r_s[i*3+2];
        float v;
        if      (comp == 0) v = dx;
        else if (comp == 1) v = dy;
        else if (comp == 2) v = dz;
        else {
            float o = (i == j) ? 1.f : 0.f;
            float ex = dx + o, ey = dy + o, ez = dz + o;
            v = sqrtf(ex*ex + ey*ey + ez*ez);
        }
        p4[idx] = v;
    }
    __syncthreads();

    // ---------------- stats for layer 0 ----------------
    if (t < 16) {
        float s = 0.f;
        #pragma unroll
        for (int e = 0; e < NU; e++) s += s_in[e*16 + t];
        mu[t] = s * 0.125f;
    } else if (t < 32) {
        int f = t - 16; float s = 0.f;
        #pragma unroll
        for (int e = NU; e < NE; e++) s += s_in[e*16 + f];
        md[f] = s * 0.125f;
    } else if (t < 96) {
        int idx = t - 32; int j = idx >> 2, c = idx & 3; float s = 0.f;
        #pragma unroll
        for (int i = 0; i < NU; i++) s += p4[(i*16 + j)*4 + c];
        pu[j*4 + c] = s * 0.125f;
    } else if (t < 160) {
        int idx = t - 96; int j = idx >> 2, c = idx & 3; float s = 0.f;
        #pragma unroll
        for (int i = NU; i < NE; i++) s += p4[(i*16 + j)*4 + c];
        pd[j*4 + c] = s * 0.125f;
    }
    __syncthreads();

    // ---------------- layer 0, s-stream ----------------
    {
        const int c = t;
        float common = sb0[c];
        #pragma unroll
        for (int k = 0; k < 16; k++)
            common += mu[k] * sW0[(16 + k)*NSV + c] + md[k] * sW0[(32 + k)*NSV + c];
        float acc[NE];
        #pragma unroll
        for (int e = 0; e < NE; e++) acc[e] = 0.f;
        #pragma unroll
        for (int k = 0; k < 16; k++) {
            float w = sW0[k*NSV + c];
            #pragma unroll
            for (int e = 0; e < NE; e++) acc[e] += s_in[e*16 + k] * w;
        }
        #pragma unroll
        for (int k = 0; k < 4; k++) {
            float wA = sW0[(48 + k)*NSV + c];
            float wB = sW0[(52 + k)*NSV + c];
            #pragma unroll
            for (int e = 0; e < NE; e++)
                acc[e] += pu[e*4 + k] * wA + pd[e*4 + k] * wB;
        }
        #pragma unroll
        for (int e = 0; e < NE; e++)
            s_v[e*NSV + c] = tanh_fast(acc[e] + common);
    }
    // ---------------- layer 0, p-stream (weights hoisted) ----------------
    {
        const int c = t & 31, wp = t >> 5;
        float w0 = pW0[0*NPV + c], w1 = pW0[1*NPV + c];
        float w2 = pW0[2*NPV + c], w3 = pW0[3*NPV + c];
        const float pbias = pb0[c];
        for (int pr = wp; pr < 256; pr += 8) {
            float4 q = *(const float4*)(p4 + pr*4);
            p_v[pr*NPV + c] = tanh_fast(pbias + q.x*w0 + q.y*w1 + q.z*w2 + q.w*w3);
        }
    }
    __syncthreads();

    // ---------------- stats after layer 0 ----------------
    {
        const int c = t;
        float su = 0.f, sd2 = 0.f;
        #pragma unroll
        for (int e = 0; e < NU; e++)  su  += s_v[e*NSV + c];
        #pragma unroll
        for (int e = NU; e < NE; e++) sd2 += s_v[e*NSV + c];
        mu[c] = su * 0.125f; md[c] = sd2 * 0.125f;
        for (int idx = t; idx < 512; idx += 256) {
            int j = idx >> 5, c2 = idx & 31;
            float pa = 0.f, pb2 = 0.f;
            #pragma unroll
            for (int i = 0; i < NU; i++)  pa  += p_v[(i*16 + j)*NPV + c2];
            #pragma unroll
            for (int i = NU; i < NE; i++) pb2 += p_v[(i*16 + j)*NPV + c2];
            pu[idx] = pa * 0.125f; pd[idx] = pb2 * 0.125f;
        }
    }
    __syncthreads();

    // ---------------- residual layers + final v layer ----------------
    // thread -> (electron half, column pair):
    const int eh    = t >> 7;          // 0: electrons 0..7, 1: electrons 8..15
    const int c0    = t & 127;
    const int cA    = 2 * c0;          // adjacent columns -> LDG.64 / STS.64
    const int ebase = eh * 8;

    for (int L = 0; L <= NFB; L++) {
        const bool isV = (L == NFB);
        const float* W    = isV ? vW : (sW + (size_t)L * SVO * NSV);
        const float* bias = isV ? vb : (sb + L * NSV);

        // ---- split common: eh=0 handles the mu block, eh=1 the md block ----
        {
            const float* stat = eh ? md : mu;
            const float* Wblk = W + (eh ? 512 : 256) * NSV + cA;
            float ca = 0.f, cb = 0.f;
            for (int k = 0; k < 256; k += 4) {
                float4 m4 = *(const float4*)(stat + k);
                float2 q0 = *(const float2*)(Wblk + (k+0)*NSV);
                float2 q1 = *(const float2*)(Wblk + (k+1)*NSV);
                float2 q2 = *(const float2*)(Wblk + (k+2)*NSV);
                float2 q3 = *(const float2*)(Wblk + (k+3)*NSV);
                ca += m4.x*q0.x + m4.y*q1.x + m4.z*q2.x + m4.w*q3.x;
                cb += m4.x*q0.y + m4.y*q1.y + m4.z*q2.y + m4.w*q3.y;
            }
            if (eh == 0) {
                float2 b2 = *(const float2*)(bias + cA);
                ca += b2.x; cb += b2.y;
            }
            float2 cv; cv.x = ca; cv.y = cb;
            *(float2*)(com + (eh << 8) + cA) = cv;
        }

        // ---- main GEMM: 8 electrons x 2 adjacent columns ----
        float accA[8], accB[8];
        #pragma unroll
        for (int e = 0; e < 8; e++) { accA[e] = 0.f; accB[e] = 0.f; }
        {
            const float* Wc = W + cA;
            for (int k = 0; k < 256; k += 4) {
                float2 w0 = *(const float2*)(Wc + (k+0)*NSV);
                float2 w1 = *(const float2*)(Wc + (k+1)*NSV);
                float2 w2 = *(const float2*)(Wc + (k+2)*NSV);
                float2 w3 = *(const float2*)(Wc + (k+3)*NSV);
                #pragma unroll
                for (int e = 0; e < 8; e++) {
                    float4 s4 = *(const float4*)(s_v + (ebase+e)*NSV + k);
                    accA[e] += s4.x*w0.x + s4.y*w1.x + s4.z*w2.x + s4.w*w3.x;
                    accB[e] += s4.x*w0.y + s4.y*w1.y + s4.z*w2.y + s4.w*w3.y;
                }
            }
        }
        {
            const float* Wpu = W + 768*NSV + cA;
            const float* Wpd = W + 800*NSV + cA;
            for (int k = 0; k < 32; k += 4) {
                float2 u0 = *(const float2*)(Wpu + (k+0)*NSV);
                float2 u1 = *(const float2*)(Wpu + (k+1)*NSV);
                float2 u2 = *(const float2*)(Wpu + (k+2)*NSV);
                float2 u3 = *(const float2*)(Wpu + (k+3)*NSV);
                float2 v0 = *(const float2*)(Wpd + (k+0)*NSV);
                float2 v1 = *(const float2*)(Wpd + (k+1)*NSV);
                float2 v2 = *(const float2*)(Wpd + (k+2)*NSV);
                float2 v3 = *(const float2*)(Wpd + (k+3)*NSV);
                #pragma unroll
                for (int e = 0; e < 8; e++) {
                    float4 a4 = *(const float4*)(pu + (ebase+e)*NPV + k);
                    float4 b4 = *(const float4*)(pd + (ebase+e)*NPV + k);
                    accA[e] += a4.x*u0.x + a4.y*u1.x + a4.z*u2.x + a4.w*u3.x
                             + b4.x*v0.x + b4.y*v1.x + b4.z*v2.x + b4.w*v3.x;
                    accB[e] += a4.x*u0.y + a4.y*u1.y + a4.z*u2.y + a4.w*u3.y
                             + b4.x*v0.y + b4.y*v1.y + b4.z*v2.y + b4.w*v3.y;
                }
            }
        }

        if (!isV) {
            // p-stream residual layer: weights hoisted into registers once
            const int c2 = t & 31, wp = t >> 5;
            const float* PW = pW + L * NPV * NPV + c2;
            float pw[32];
            #pragma unroll
            for (int k = 0; k < 32; k++) pw[k] = PW[k*NPV];
            const float pbias = pb[L*NPV + c2];
            for (int pr = wp; pr < 256; pr += 8) {
                float pacc = pbias;
                #pragma unroll
                for (int k = 0; k < 32; k += 4) {
                    float4 v4 = *(const float4*)(p_v + pr*NPV + k);
                    pacc += v4.x*pw[k] + v4.y*pw[k+1] + v4.z*pw[k+2] + v4.w*pw[k+3];
                }
                p_v[pr*NPV + c2] = tanh_fast(pacc) + p_v[pr*NPV + c2];
            }
        }

        __syncthreads();   // s_v reads + com writes complete
        {
            float2 cm0 = *(const float2*)(com + cA);
            float2 cm1 = *(const float2*)(com + 256 + cA);
            const float cmA = cm0.x + cm1.x;
            const float cmB = cm0.y + cm1.y;
            if (!isV) {
                #pragma unroll
                for (int e = 0; e < 8; e++) {
                    float* dst = s_v + (ebase+e)*NSV + cA;
                    float2 old = *(const float2*)dst;
                    float2 nv;
                    nv.x = tanh_fast(accA[e] + cmA) + old.x;
                    nv.y = tanh_fast(accB[e] + cmB) + old.y;
                    *(float2*)dst = nv;
                }
            } else {
                #pragma unroll
                for (int e = 0; e < 8; e++) {
                    float2 nv;
                    nv.x = tanh_fast(accA[e] + cmA);
                    nv.y = tanh_fast(accB[e] + cmB);
                    *(float2*)(s_v + (ebase+e)*NSV + cA) = nv;
                }
            }
        }
        __syncthreads();

        if (!isV) {
            const int c = t;
            float su = 0.f, sd2 = 0.f;
            #pragma unroll
            for (int e = 0; e < NU; e++)  su  += s_v[e*NSV + c];
            #pragma unroll
            for (int e = NU; e < NE; e++) sd2 += s_v[e*NSV + c];
            mu[c] = su * 0.125f; md[c] = sd2 * 0.125f;
            for (int idx = t; idx < 512; idx += 256) {
                int j = idx >> 5, cc = idx & 31;
                float pa = 0.f, pb2 = 0.f;
                #pragma unroll
                for (int i = 0; i < NU; i++)  pa  += p_v[(i*16 + j)*NPV + cc];
                #pragma unroll
                for (int i = NU; i < NE; i++) pb2 += p_v[(i*16 + j)*NPV + cc];
                pu[idx] = pa * 0.125f; pd[idx] = pb2 * 0.125f;
            }
            __syncthreads();
        }
    }
    // NOTE: p_v is dead from here on; detS aliases its storage.

    // ---------------- orbitals (k-outer, weights loaded once) ----------------
    {
        const bool up = (t < 128);
        const int col = up ? t : t - 128;
        const float* W    = up ? wuW : wdW;
        const float* bias = up ? wub : wdb;
        const int eb2 = up ? 0 : NU;
        const int d = col & 15, j = col >> 4;
        const int detIdx = (up ? 0 : NDET) + d;

        float acc[8];
        #pragma unroll
        for (int ii = 0; ii < 8; ii++) acc[ii] = 0.f;
        for (int k = 0; k < 256; k += 4) {
            float w0 = W[(k+0)*128 + col];
            float w1 = W[(k+1)*128 + col];
            float w2 = W[(k+2)*128 + col];
            float w3 = W[(k+3)*128 + col];
            #pragma unroll
            for (int ii = 0; ii < 8; ii++) {
                float4 s4 = *(const float4*)(s_v + (eb2+ii)*NSV + k);
                acc[ii] += s4.x*w0 + s4.y*w1 + s4.z*w2 + s4.w*w3;
            }
        }
        float bs = bias[col];
        #pragma unroll
        for (int ii = 0; ii < 8; ii++)
            detS[detIdx*65 + ii*8 + j] = (acc[ii] + bs) * env[eb2 + ii];
    }
    __syncthreads();

    // ---------------- slogdet: 8x8 LU with partial pivoting ----------------
    if (t < 32) {
        float* M = detS + t * 65;
        float sg = 1.f, ld = 0.f;
        for (int k = 0; k < 8; k++) {
            int p = k; float best = fabsf(M[k*8 + k]);
            for (int rr2 = k + 1; rr2 < 8; rr2++) {
                float v = fabsf(M[rr2*8 + k]);
                if (v > best) { best = v; p = rr2; }
            }
            if (p != k) {
                for (int cc = 0; cc < 8; cc++) {
                    float tmp = M[k*8 + cc]; M[k*8 + cc] = M[p*8 + cc]; M[p*8 + cc] = tmp;
                }
                sg = -sg;
            }
            float piv = M[k*8 + k];
            if (piv < 0.f) sg = -sg;
            ld += logf(fabsf(piv));
            float inv = 1.f / piv;
            for (int rr2 = k + 1; rr2 < 8; rr2++) {
                float f = M[rr2*8 + k] * inv;
                for (int cc = k + 1; cc < 8; cc++) M[rr2*8 + cc] -= f * M[k*8 + cc];
            }
        }
        logd_s[t] = ld; sign_s[t] = sg;
    }
    __syncthreads();

    // ---------------- combine ----------------
    if (t == 0) {
        float lds[NDET], sgs[NDET], m = -1e30f;
        #pragma unroll
        for (int d = 0; d < NDET; d++) {
            lds[d] = logd_s[d] + logd_s[NDET + d];
            sgs[d] = sign_s[d] * sign_s[NDET + d];
            if (lds[d] > m) m = lds[d];
        }
        float sum = 0.f;
        #pragma unroll
        for (int d = 0; d < NDET; d++)
            sum += sgs[d] * expf(lds[d] - m) * wfW[d];
        out[b] = logf(fabsf(sum)) + m;
    }
}

extern "C" void kernel_launch(void* const* d_in, const int* in_sizes, int n_in,
                              void* d_out, int out_size)
{
    const float* r   = (const float*)d_in[0];
    const float* a   = (const float*)d_in[1];
    const float* sW0 = (const float*)d_in[2];
    const float* sb0 = (const float*)d_in[3];
    const float* sW  = (const float*)d_in[4];
    const float* sb  = (const float*)d_in[5];
    const float* pW0 = (const float*)d_in[6];
    const float* pb0 = (const float*)d_in[7];
    const float* pW  = (const float*)d_in[8];
    const float* pb  = (const float*)d_in[9];
    const float* vW  = (const float*)d_in[10];
    const float* vb  = (const float*)d_in[11];
    const float* wuW = (const float*)d_in[12];
    const float* wub = (const float*)d_in[13];
    const float* wdW = (const float*)d_in[14];
    const float* wdb = (const float*)d_in[15];
    const float* wfW = (const float*)d_in[16];
    float* out = (float*)d_out;

    const int B = in_sizes[0] / (NE * 3);

    cudaFuncSetAttribute(ansatz_kernel,
                         cudaFuncAttributeMaxDynamicSharedMemorySize, SMEM_BYTES);
    ansatz_kernel<<<B, 256, SMEM_BYTES>>>(r, a, sW0, sb0, sW, sb, pW0, pb0,
                                          pW, pb, vW, vb, wuW, wub, wdW, wdb,
                                          wfW, out);
}

// round 6
// speedup vs baseline: 1.4256x; 1.0363x over previous
#include <cuda_runtime.h>
#include <math.h>

#define NE   16
#define NU   8
#define NA   4
#define NSV  256
#define NPV  32
#define NFB  4
#define NDET 16
#define SVO  832   // 3*256 + 2*32

// shared layout (floats) — exactly 14336 floats = 57344 B (4 CTAs/SM)
#define OFF_SV    0        // 16*256 = 4096
#define OFF_PV    4096     // 256*32 = 8192   (s_in + detS alias here)
#define OFF_MU    12288    // 256             (logd/sign/env alias here at the end)
#define OFF_MD    12544    // 256
#define OFF_PU    12800    // 16*32 = 512
#define OFF_PD    13312    // 512
#define OFF_COM   13824    // 512             (r_s/a_s alias here early)
#define SMEM_FLOATS 14336
#define SMEM_BYTES  (SMEM_FLOATS * 4)

__device__ __forceinline__ float tanh_fast(float x) {
    // no clamp needed: __expf(+inf)=inf -> 1-0=1 ; __expf(-inf)=0 -> 1-2=-1
    float e = __expf(2.0f * x);
    return 1.0f - __fdividef(2.0f, e + 1.0f);
}

__global__ void __launch_bounds__(256, 4) ansatz_kernel(
    const float* __restrict__ r,    const float* __restrict__ a,
    const float* __restrict__ sW0,  const float* __restrict__ sb0,
    const float* __restrict__ sW,   const float* __restrict__ sb,
    const float* __restrict__ pW0,  const float* __restrict__ pb0,
    const float* __restrict__ pW,   const float* __restrict__ pb,
    const float* __restrict__ vW,   const float* __restrict__ vb,
    const float* __restrict__ wuW,  const float* __restrict__ wub,
    const float* __restrict__ wdW,  const float* __restrict__ wdb,
    const float* __restrict__ wfW,  float* __restrict__ out)
{
    extern __shared__ float sm[];
    float* s_v  = sm + OFF_SV;
    float* p_v  = sm + OFF_PV;
    float* mu   = sm + OFF_MU;
    float* md   = sm + OFF_MD;
    float* pu   = sm + OFF_PU;
    float* pd   = sm + OFF_PD;
    float* com  = sm + OFF_COM;

    // early-phase aliases (regions dead at time of use)
    float* s_in = sm + OFF_PV;          // [0:256) of p_v, dead before p_v is written
    float* r_s  = sm + OFF_COM;         // 48, dead before com first written (layer 1 phase A)
    float* a_s  = sm + OFF_COM + 48;    // 12
    // late-phase aliases (mu dead after v-layer; p_v dead after last p-stream)
    float* detS   = sm + OFF_PV;        // 32*65 = 2080 <= 8192
    float* logd_s = sm + OFF_MU;        // 32
    float* sign_s = sm + OFF_MU + 32;   // 32
    float* env    = sm + OFF_MU + 64;   // 16

    const int t = threadIdx.x;
    const int b = blockIdx.x;

    if (t < 48)              r_s[t]      = r[b * 48 + t];
    if (t >= 64 && t < 76)   a_s[t - 64] = a[t - 64];
    __syncthreads();

    // ---------------- embedding: s_in only (rr recomputed on demand) ----------------
    {
        int e = t >> 4, f = t & 15, atom = f >> 2, comp = f & 3;
        float dx = r_s[e*3+0] - a_s[atom*3+0];
        float dy = r_s[e*3+1] - a_s[atom*3+1];
        float dz = r_s[e*3+2] - a_s[atom*3+2];
        float v;
        if      (comp == 0) v = dx;
        else if (comp == 1) v = dy;
        else if (comp == 2) v = dz;
        else                v = sqrtf(dx*dx + dy*dy + dz*dz);
        s_in[t] = v;
    }
    __syncthreads();

    // ---------------- stats for layer 0 (mu/md 16-wide, pu/pd 4-wide) ----------------
    if (t < 16) {
        float s = 0.f;
        #pragma unroll
        for (int e = 0; e < NU; e++) s += s_in[e*16 + t];
        mu[t] = s * 0.125f;
    } else if (t < 32) {
        int f = t - 16; float s = 0.f;
        #pragma unroll
        for (int e = NU; e < NE; e++) s += s_in[e*16 + f];
        md[f] = s * 0.125f;
    } else if (t < 160) {
        int idx = t - 32;
        int half = idx >> 6;           // 0: up (i<8), 1: down (i>=8)
        idx &= 63;
        int j = idx >> 2, c = idx & 3;
        int ib = half * 8;
        float rjx = r_s[j*3+0], rjy = r_s[j*3+1], rjz = r_s[j*3+2];
        float s = 0.f;
        #pragma unroll
        for (int ii = 0; ii < 8; ii++) {
            int i = ib + ii;
            float dx = rjx - r_s[i*3+0];
            float dy = rjy - r_s[i*3+1];
            float dz = rjz - r_s[i*3+2];
            float v;
            if      (c == 0) v = dx;
            else if (c == 1) v = dy;
            else if (c == 2) v = dz;
            else {
                float o = (i == j) ? 1.f : 0.f;
                float ex = dx + o, ey = dy + o, ez = dz + o;
                v = sqrtf(ex*ex + ey*ey + ez*ez);
            }
            s += v;
        }
        if (half == 0) pu[j*4 + c] = s * 0.125f;
        else           pd[j*4 + c] = s * 0.125f;
    }
    __syncthreads();

    // ---------------- layer 0, s-stream (reads s_in; mu/md stats fused to regs) ----------------
    float smu, smd;   // new mu/md contributions (stored after next barrier)
    {
        const int c = t;
        float common = sb0[c];
        #pragma unroll
        for (int k = 0; k < 16; k++)
            common += mu[k] * sW0[(16 + k)*NSV + c] + md[k] * sW0[(32 + k)*NSV + c];
        float acc[NE];
        #pragma unroll
        for (int e = 0; e < NE; e++) acc[e] = 0.f;
        #pragma unroll
        for (int k = 0; k < 16; k++) {
            float w = sW0[k*NSV + c];
            #pragma unroll
            for (int e = 0; e < NE; e++) acc[e] += s_in[e*16 + k] * w;
        }
        #pragma unroll
        for (int k = 0; k < 4; k++) {
            float wA = sW0[(48 + k)*NSV + c];
            float wB = sW0[(52 + k)*NSV + c];
            #pragma unroll
            for (int e = 0; e < NE; e++)
                acc[e] += pu[e*4 + k] * wA + pd[e*4 + k] * wB;
        }
        smu = 0.f; smd = 0.f;
        #pragma unroll
        for (int e = 0; e < NE; e++) {
            float v = tanh_fast(acc[e] + common);
            s_v[e*NSV + c] = v;
            if (e < NU) smu += v; else smd += v;
        }
    }
    __syncthreads();   // s_in reads done; p_v region may now be written

    // ---------------- layer 0, p-stream (rr recomputed; pu/pd stats fused) ----------------
    {
        const int c2 = t & 31, wp = t >> 5;
        float w0 = pW0[0*NPV + c2], w1 = pW0[1*NPV + c2];
        float w2 = pW0[2*NPV + c2], w3 = pW0[3*NPV + c2];
        const float pbias = pb0[c2];
        float puA = 0.f, puB = 0.f, pdA = 0.f, pdB = 0.f;
        for (int pr = wp; pr < 256; pr += 8) {
            int i = pr >> 4, j = pr & 15;
            float dx = r_s[j*3+0] - r_s[i*3+0];
            float dy = r_s[j*3+1] - r_s[i*3+1];
            float dz = r_s[j*3+2] - r_s[i*3+2];
            float o = (i == j) ? 1.f : 0.f;
            float ex = dx + o, ey = dy + o, ez = dz + o;
            float len = sqrtf(ex*ex + ey*ey + ez*ez);
            float v = tanh_fast(pbias + dx*w0 + dy*w1 + dz*w2 + len*w3);
            p_v[pr*NPV + c2] = v;
            bool jA = ((pr >> 3) & 1) == 0;   // j == wp ?
            if (i < NU) { if (jA) puA += v; else puB += v; }
            else        { if (jA) pdA += v; else pdB += v; }
        }
        pu[wp*NPV + c2]       = puA * 0.125f;
        pu[(wp+8)*NPV + c2]   = puB * 0.125f;
        pd[wp*NPV + c2]       = pdA * 0.125f;
        pd[(wp+8)*NPV + c2]   = pdB * 0.125f;
        mu[t] = smu * 0.125f;
        md[t] = smd * 0.125f;
    }
    __syncthreads();

    // ---------------- residual layers + final v layer ----------------
    const int eh    = t >> 7;          // 0: electrons 0..7, 1: electrons 8..15
    const int c0    = t & 127;
    const int cA    = 2 * c0;          // adjacent columns -> 64-bit accesses
    const int ebase = eh * 8;

    for (int L = 0; L <= NFB; L++) {
        const bool isV = (L == NFB);
        const float* W    = isV ? vW : (sW + (size_t)L * SVO * NSV);
        const float* bias = isV ? vb : (sb + L * NSV);

        float puA = 0.f, puB = 0.f, pdA = 0.f, pdB = 0.f;
        if (!isV) {
            // p-stream residual layer FIRST (frees its registers before main GEMM).
            // In-place p_v update is safe: columns are lane-private within the owning warp.
            const int c2 = t & 31, wp = t >> 5;
            const float* PW = pW + L * NPV * NPV + c2;
            float pw[32];
            #pragma unroll
            for (int k = 0; k < 32; k++) pw[k] = PW[k*NPV];
            const float pbias = pb[L*NPV + c2];
            for (int pr = wp; pr < 256; pr += 8) {
                float pacc = pbias;
                #pragma unroll
                for (int k = 0; k < 32; k += 4) {
                    float4 v4 = *(const float4*)(p_v + pr*NPV + k);
                    pacc += v4.x*pw[k] + v4.y*pw[k+1] + v4.z*pw[k+2] + v4.w*pw[k+3];
                }
                float v = tanh_fast(pacc) + p_v[pr*NPV + c2];
                p_v[pr*NPV + c2] = v;
                bool jA = ((pr >> 3) & 1) == 0;
                if ((pr >> 4) < NU) { if (jA) puA += v; else puB += v; }
                else                { if (jA) pdA += v; else pdB += v; }
            }
        }

        // ---- split common: eh=0 handles the mu block, eh=1 the md block ----
        {
            const float* stat = eh ? md : mu;
            const float* Wblk = W + (eh ? 512 : 256) * NSV + cA;
            float ca = 0.f, cb = 0.f;
            for (int k = 0; k < 256; k += 4) {
                float4 m4 = *(const float4*)(stat + k);
                float2 q0 = *(const float2*)(Wblk + (k+0)*NSV);
                float2 q1 = *(const float2*)(Wblk + (k+1)*NSV);
                float2 q2 = *(const float2*)(Wblk + (k+2)*NSV);
                float2 q3 = *(const float2*)(Wblk + (k+3)*NSV);
                ca += m4.x*q0.x + m4.y*q1.x + m4.z*q2.x + m4.w*q3.x;
                cb += m4.x*q0.y + m4.y*q1.y + m4.z*q2.y + m4.w*q3.y;
            }
            if (eh == 0) {
                float2 b2 = *(const float2*)(bias + cA);
                ca += b2.x; cb += b2.y;
            }
            float2 cv; cv.x = ca; cv.y = cb;
            *(float2*)(com + (eh << 8) + cA) = cv;
        }

        // ---- main GEMM: 8 electrons x 2 adjacent columns ----
        float accA[8], accB[8];
        #pragma unroll
        for (int e = 0; e < 8; e++) { accA[e] = 0.f; accB[e] = 0.f; }
        {
            const float* Wc = W + cA;
            for (int k = 0; k < 256; k += 4) {
                float2 w0 = *(const float2*)(Wc + (k+0)*NSV);
                float2 w1 = *(const float2*)(Wc + (k+1)*NSV);
                float2 w2 = *(const float2*)(Wc + (k+2)*NSV);
                float2 w3 = *(const float2*)(Wc + (k+3)*NSV);
                #pragma unroll
                for (int e = 0; e < 8; e++) {
                    float4 s4 = *(const float4*)(s_v + (ebase+e)*NSV + k);
                    accA[e] += s4.x*w0.x + s4.y*w1.x + s4.z*w2.x + s4.w*w3.x;
                    accB[e] += s4.x*w0.y + s4.y*w1.y + s4.z*w2.y + s4.w*w3.y;
                }
            }
        }
        {
            const float* Wpu = W + 768*NSV + cA;
            const float* Wpd = W + 800*NSV + cA;
            for (int k = 0; k < 32; k += 4) {
                float2 u0 = *(const float2*)(Wpu + (k+0)*NSV);
                float2 u1 = *(const float2*)(Wpu + (k+1)*NSV);
                float2 u2 = *(const float2*)(Wpu + (k+2)*NSV);
                float2 u3 = *(const float2*)(Wpu + (k+3)*NSV);
                float2 v0 = *(const float2*)(Wpd + (k+0)*NSV);
                float2 v1 = *(const float2*)(Wpd + (k+1)*NSV);
                float2 v2 = *(const float2*)(Wpd + (k+2)*NSV);
                float2 v3 = *(const float2*)(Wpd + (k+3)*NSV);
                #pragma unroll
                for (int e = 0; e < 8; e++) {
                    float4 a4 = *(const float4*)(pu + (ebase+e)*NPV + k);
                    float4 b4 = *(const float4*)(pd + (ebase+e)*NPV + k);
                    accA[e] += a4.x*u0.x + a4.y*u1.x + a4.z*u2.x + a4.w*u3.x
                             + b4.x*v0.x + b4.y*v1.x + b4.z*v2.x + b4.w*v3.x;
                    accB[e] += a4.x*u0.y + a4.y*u1.y + a4.z*u2.y + a4.w*u3.y
                             + b4.x*v0.y + b4.y*v1.y + b4.z*v2.y + b4.w*v3.y;
                }
            }
        }

        __syncthreads();   // s_v/pu/pd reads + com writes complete

        // ---- writeback + fused mu/md stats; deferred pu/pd stores ----
        {
            float2 cm0 = *(const float2*)(com + cA);
            float2 cm1 = *(const float2*)(com + 256 + cA);
            const float cmA = cm0.x + cm1.x;
            const float cmB = cm0.y + cm1.y;
            float sA = 0.f, sB = 0.f;
            if (!isV) {
                #pragma unroll
                for (int e = 0; e < 8; e++) {
                    float* dst = s_v + (ebase+e)*NSV + cA;
                    float2 old = *(const float2*)dst;
                    float2 nv;
                    nv.x = tanh_fast(accA[e] + cmA) + old.x;
                    nv.y = tanh_fast(accB[e] + cmB) + old.y;
                    *(float2*)dst = nv;
                    sA += nv.x; sB += nv.y;
                }
                // this half's 8 electrons == exactly the mean needed
                float* statdst = eh ? md : mu;
                float2 sv2; sv2.x = sA * 0.125f; sv2.y = sB * 0.125f;
                *(float2*)(statdst + cA) = sv2;
                // deferred p-stats
                const int c2 = t & 31, wp = t >> 5;
                pu[wp*NPV + c2]     = puA * 0.125f;
                pu[(wp+8)*NPV + c2] = puB * 0.125f;
                pd[wp*NPV + c2]     = pdA * 0.125f;
                pd[(wp+8)*NPV + c2] = pdB * 0.125f;
            } else {
                #pragma unroll
                for (int e = 0; e < 8; e++) {
                    float2 nv;
                    nv.x = tanh_fast(accA[e] + cmA);
                    nv.y = tanh_fast(accB[e] + cmB);
                    *(float2*)(s_v + (ebase+e)*NSV + cA) = nv;
                }
                // env recompute (mu region is dead now); r/a reloaded from global
                if (t < 16) {
                    const float* rg = r + b*48 + t*3;
                    float ex = rg[0], ey = rg[1], ez = rg[2];
                    float s = 0.f;
                    #pragma unroll
                    for (int atom = 0; atom < NA; atom++) {
                        float dx = ex - a[atom*3+0];
                        float dy = ey - a[atom*3+1];
                        float dz = ez - a[atom*3+2];
                        s += __expf(-sqrtf(dx*dx + dy*dy + dz*dz));
                    }
                    env[t] = s;
                }
            }
        }
        __syncthreads();
    }
    // NOTE: p_v is dead from here on; detS aliases its storage.

    // ---------------- orbitals (k-outer, weights loaded once) ----------------
    {
        const bool up = (t < 128);
        const int col = up ? t : t - 128;
        const float* W    = up ? wuW : wdW;
        const float* bias = up ? wub : wdb;
        const int eb2 = up ? 0 : NU;
        const int d = col & 15, j = col >> 4;
        const int detIdx = (up ? 0 : NDET) + d;

        float acc[8];
        #pragma unroll
        for (int ii = 0; ii < 8; ii++) acc[ii] = 0.f;
        for (int k = 0; k < 256; k += 4) {
            float w0 = W[(k+0)*128 + col];
            float w1 = W[(k+1)*128 + col];
            float w2 = W[(k+2)*128 + col];
            float w3 = W[(k+3)*128 + col];
            #pragma unroll
            for (int ii = 0; ii < 8; ii++) {
                float4 s4 = *(const float4*)(s_v + (eb2+ii)*NSV + k);
                acc[ii] += s4.x*w0 + s4.y*w1 + s4.z*w2 + s4.w*w3;
            }
        }
        float bs = bias[col];
        #pragma unroll
        for (int ii = 0; ii < 8; ii++)
            detS[detIdx*65 + ii*8 + j] = (acc[ii] + bs) * env[eb2 + ii];
    }
    __syncthreads();

    // ---------------- slogdet: 8x8 LU with partial pivoting ----------------
    if (t < 32) {
        float* M = detS + t * 65;
        float sg = 1.f, ld = 0.f;
        for (int k = 0; k < 8; k++) {
            int p = k; float best = fabsf(M[k*8 + k]);
            for (int rr2 = k + 1; rr2 < 8; rr2++) {
                float v = fabsf(M[rr2*8 + k]);
                if (v > best) { best = v; p = rr2; }
            }
            if (p != k) {
                for (int cc = 0; cc < 8; cc++) {
                    float tmp = M[k*8 + cc]; M[k*8 + cc] = M[p*8 + cc]; M[p*8 + cc] = tmp;
                }
                sg = -sg;
            }
            float piv = M[k*8 + k];
            if (piv < 0.f) sg = -sg;
            ld += logf(fabsf(piv));
            float inv = 1.f / piv;
            for (int rr2 = k + 1; rr2 < 8; rr2++) {
                float f = M[rr2*8 + k] * inv;
                for (int cc = k + 1; cc < 8; cc++) M[rr2*8 + cc] -= f * M[k*8 + cc];
            }
        }
        logd_s[t] = ld; sign_s[t] = sg;
    }
    __syncthreads();

    // ---------------- combine ----------------
    if (t == 0) {
        float lds[NDET], sgs[NDET], m = -1e30f;
        #pragma unroll
        for (int d = 0; d < NDET; d++) {
            lds[d] = logd_s[d] + logd_s[NDET + d];
            sgs[d] = sign_s[d] * sign_s[NDET + d];
            if (lds[d] > m) m = lds[d];
        }
        float sum = 0.f;
        #pragma unroll
        for (int d = 0; d < NDET; d++)
            sum += sgs[d] * expf(lds[d] - m) * wfW[d];
        out[b] = logf(fabsf(sum)) + m;
    }
}

extern "C" void kernel_launch(void* const* d_in, const int* in_sizes, int n_in,
                              void* d_out, int out_size)
{
    const float* r   = (const float*)d_in[0];
    const float* a   = (const float*)d_in[1];
    const float* sW0 = (const float*)d_in[2];
    const float* sb0 = (const float*)d_in[3];
    const float* sW  = (const float*)d_in[4];
    const float* sb  = (const float*)d_in[5];
    const float* pW0 = (const float*)d_in[6];
    const float* pb0 = (const float*)d_in[7];
    const float* pW  = (const float*)d_in[8];
    const float* pb  = (const float*)d_in[9];
    const float* vW  = (const float*)d_in[10];
    const float* vb  = (const float*)d_in[11];
    const float* wuW = (const float*)d_in[12];
    const float* wub = (const float*)d_in[13];
    const float* wdW = (const float*)d_in[14];
    const float* wdb = (const float*)d_in[15];
    const float* wfW = (const float*)d_in[16];
    float* out = (float*)d_out;

    const int B = in_sizes[0] / (NE * 3);

    cudaFuncSetAttribute(ansatz_kernel,
                         cudaFuncAttributeMaxDynamicSharedMemorySize, SMEM_BYTES);
    ansatz_kernel<<<B, 256, SMEM_BYTES>>>(r, a, sW0, sb0, sW, sb, pW0, pb0,
                                          pW, pb, vW, vb, wuW, wub, wdW, wdb,
                                          wfW, out);
}